// round 6
// baseline (speedup 1.0000x reference)
#include <cuda_runtime.h>

// score[e] = sum_d h[src[e], d] * h[dst[e], d]
// h: [100000, 32] fp32 ; src/dst: int32 [E] ; out: fp32 [E]
//
// 8 lanes per group, 8 edges per group:
//  - 2x int4 broadcast index loads per side (8 src + 8 dst idx per group)
//  - 16 float4 gathers; each 8-lane group touches exactly one 128B line per
//    gathered row (2 L1tex wavefronts/edge = structural floor; within-LDG
//    replay at ~2.07 cyc/line is the binding rate)
//  - value-halving shuffle reduction: 7 shuffles for 8 edge-sums; the final
//    sum for edge e0+i lands on lane i -> dense unpredicated 8-lane store

static constexpr int D = 32;
static constexpr int EPG = 8;          // edges per 8-lane group
static constexpr unsigned FULL = 0xFFFFFFFFu;

__device__ __forceinline__ float dot4(float4 a, float4 b) {
    return a.x * b.x + a.y * b.y + a.z * b.z + a.w * b.w;
}

__device__ __forceinline__ float red8(float p) {
    p += __shfl_xor_sync(FULL, p, 1);
    p += __shfl_xor_sync(FULL, p, 2);
    p += __shfl_xor_sync(FULL, p, 4);
    return p;
}

__device__ __forceinline__ float4 grow(const float* __restrict__ h, int idx, int i) {
    return reinterpret_cast<const float4*>(h + (long long)idx * D)[i];
}

__global__ __launch_bounds__(256, 6) void edge_dot_kernel(
    const float* __restrict__ h,
    const int* __restrict__ src,
    const int* __restrict__ dst,
    float* __restrict__ out,
    int E)
{
    int gid = blockIdx.x * blockDim.x + threadIdx.x;
    int g = gid >> 3;                 // 8-lane group index
    int i = gid & 7;                  // lane within group
    long long e0 = (long long)g * EPG;
    if (e0 >= E) return;

    if (e0 + EPG <= E) {
        const int4* s4 = reinterpret_cast<const int4*>(src + e0);
        const int4* d4 = reinterpret_cast<const int4*>(dst + e0);
        int4 sa = s4[0], sb = s4[1];
        int4 da = d4[0], db = d4[1];

        float p0 = dot4(grow(h, sa.x, i), grow(h, da.x, i));
        float p1 = dot4(grow(h, sa.y, i), grow(h, da.y, i));
        float p2 = dot4(grow(h, sa.z, i), grow(h, da.z, i));
        float p3 = dot4(grow(h, sa.w, i), grow(h, da.w, i));
        float p4 = dot4(grow(h, sb.x, i), grow(h, db.x, i));
        float p5 = dot4(grow(h, sb.y, i), grow(h, db.y, i));
        float p6 = dot4(grow(h, sb.z, i), grow(h, db.z, i));
        float p7 = dot4(grow(h, sb.w, i), grow(h, db.w, i));

        // --- value-halving reduction: 8 values over 8 lanes, 7 shuffles ---
        // level xor-4: 8 -> 4 (low lanes keep p0..p3, high keep p4..p7)
        bool hi4 = (i & 4) != 0;
        float u0 = hi4 ? p0 : p4;  float v0 = __shfl_xor_sync(FULL, u0, 4);
        float u1 = hi4 ? p1 : p5;  float v1 = __shfl_xor_sync(FULL, u1, 4);
        float u2 = hi4 ? p2 : p6;  float v2 = __shfl_xor_sync(FULL, u2, 4);
        float u3 = hi4 ? p3 : p7;  float v3 = __shfl_xor_sync(FULL, u3, 4);
        float q0 = (hi4 ? p4 : p0) + v0;
        float q1 = (hi4 ? p5 : p1) + v1;
        float q2 = (hi4 ? p6 : p2) + v2;
        float q3 = (hi4 ? p7 : p3) + v3;

        // level xor-2: 4 -> 2
        bool hi2 = (i & 2) != 0;
        float w0 = hi2 ? q0 : q2;  float x0 = __shfl_xor_sync(FULL, w0, 2);
        float w1 = hi2 ? q1 : q3;  float x1 = __shfl_xor_sync(FULL, w1, 2);
        float r0 = (hi2 ? q2 : q0) + x0;
        float r1 = (hi2 ? q3 : q1) + x1;

        // level xor-1: 2 -> 1
        bool hi1 = (i & 1) != 0;
        float y = hi1 ? r0 : r1;   float z = __shfl_xor_sync(FULL, y, 1);
        float s = (hi1 ? r1 : r0) + z;

        // lane i holds the full sum for edge e0 + i -> dense store
        out[e0 + i] = s;
    } else {
        // remainder (E not divisible by 8)
        for (long long e = e0; e < E; ++e) {
            float4 a = grow(h, src[e], i);
            float4 b = grow(h, dst[e], i);
            float p = red8(dot4(a, b));
            if (i == 0) out[e] = p;
        }
    }
}

extern "C" void kernel_launch(void* const* d_in, const int* in_sizes, int n_in,
                              void* d_out, int out_size)
{
    const float* h   = (const float*)d_in[0];
    const int*   src = (const int*)d_in[1];
    const int*   dst = (const int*)d_in[2];
    float*       out = (float*)d_out;

    int E = in_sizes[1];
    long long groups = ((long long)E + EPG - 1) / EPG;
    long long total_threads = groups * 8;
    int block = 256;
    int grid = (int)((total_threads + block - 1) / block);

    edge_dot_kernel<<<grid, block>>>(h, src, dst, out, E);
}